// round 9
// baseline (speedup 1.0000x reference)
#include <cuda_runtime.h>
#include <cuda_bf16.h>
#include <cstdint>

// Problem constants (fixed shapes from reference)
#define NB    32
#define NA    1024
#define PPB   65536      // pairs per batch = NA * NEIGH
#define NTYPE 4
#define NWAVE 16
#define NPAIR (NB * PPB)                 // 2,097,152
#define NATOM (NB * NA)                  // 32,768
#define NOUT  (NATOM * NTYPE * NWAVE)    // 2,097,152 floats
#define CAP   128                        // bucket capacity per atom (mean ~61, 8.6 sigma headroom)

// Scratch (device-global: allocation-free, module-load resident)
__device__ int   g_cnt[NATOM];
__device__ float g_bucket[(size_t)NATOM * CAP];   // 16 MB, L2-resident

// ---------------------------------------------------------------------------
// K1: zero the per-atom counters
// ---------------------------------------------------------------------------
__global__ void zero_cnt_kernel() {
    int i = blockIdx.x * blockDim.x + threadIdx.x;   // NATOM threads
    g_cnt[i] = 0;
}

// ---------------------------------------------------------------------------
// K2 (passA): per-pair distance, bucket scatter of r by center atom
// ---------------------------------------------------------------------------
__global__ void __launch_bounds__(256)
scatter_kernel(const float* __restrict__ coords,      // (NATOM, 3)
               const float* __restrict__ shifts,      // (NB*PPB, 3)
               const int*   __restrict__ atom_index)  // (NB, 2, PPB)
{
    unsigned p = blockIdx.x * blockDim.x + threadIdx.x;  // exactly NPAIR threads
    unsigned b = p >> 16;                                // PPB = 2^16
    unsigned j = p & (PPB - 1);

    const int* ai = atom_index + (size_t)b * 2u * PPB;
    int i0 = __ldg(ai + j);
    int i1 = __ldg(ai + PPB + j);
    unsigned g0 = (b << 10) + (unsigned)i0;              // NA = 2^10
    unsigned g1 = (b << 10) + (unsigned)i1;

    const float* shp = shifts + 3ull * p;                // coalesced 12B/thread
    float sx = shp[0], sy = shp[1], sz = shp[2];
    bool valid = (sx > -1e9f) && (sy > -1e9f) && (sz > -1e9f);

    const float* c0 = coords + 3ull * g0;                // 12KB/batch window -> L1 hits
    const float* c1 = coords + 3ull * g1;
    float dx = __ldg(c0 + 0) - __ldg(c1 + 0) + sx;
    float dy = __ldg(c0 + 1) - __ldg(c1 + 1) + sy;
    float dz = __ldg(c0 + 2) - __ldg(c1 + 2) + sz;
    float r = sqrtf(dx * dx + dy * dy + dz * dz);

    // zero contribution if invalid or beyond cutoff: skip entirely (fc==0 at r>=5)
    if (!valid || r >= 5.0f) return;

    int slot = atomicAdd(&g_cnt[g0], 1);
    if (slot < CAP)                                      // overflow guard (never hit for these inputs)
        g_bucket[(size_t)g0 * CAP + slot] = r;
}

// ---------------------------------------------------------------------------
// K3 (passB): one warp per atom — gather bucket, radial basis, reduce, write
//             (also performs the zero-fill and the final square)
// ---------------------------------------------------------------------------
__global__ void __launch_bounds__(256)
gather_kernel(const float* __restrict__ rs,        // (NTYPE, NWAVE)
              const float* __restrict__ inta,      // (NTYPE, NWAVE)
              const int*   __restrict__ species,   // (NATOM)
              float*       __restrict__ dens)      // (NATOM, NTYPE*NWAVE)
{
    __shared__ float s_rs[NTYPE * NWAVE];
    __shared__ float s_ia[NTYPE * NWAVE];
    int t = threadIdx.x;
    if (t < NTYPE * NWAVE) {
        s_rs[t] = rs[t];
        s_ia[t] = inta[t];
    }
    __syncthreads();

    int warp = (blockIdx.x * blockDim.x + t) >> 5;   // one warp per atom
    int lane = t & 31;
    // grid covers exactly NATOM warps

    int cnt  = g_cnt[warp];
    if (cnt > CAP) cnt = CAP;
    int spec = __ldg(species + warp);
    const float* bk  = g_bucket + (size_t)warp * CAP;
    const float* prs = s_rs + spec * NWAVE;
    const float* pia = s_ia + spec * NWAVE;

    float acc[NWAVE];
#pragma unroll
    for (int w = 0; w < NWAVE; ++w) acc[w] = 0.0f;

    for (int i = lane; i < cnt; i += 32) {
        float r  = bk[i];                            // coalesced within warp
        float fc = 0.5f * (__cosf(r * 0.628318530717958647692f) + 1.0f);
#pragma unroll
        for (int w = 0; w < NWAVE; ++w) {
            float d = r - prs[w];
            acc[w] += fc * __expf(-10.0f * pia[w] * d * d);
        }
    }

    // butterfly reduction across the warp: every lane ends with the full sums
#pragma unroll
    for (int off = 16; off >= 1; off >>= 1) {
#pragma unroll
        for (int w = 0; w < NWAVE; ++w)
            acc[w] += __shfl_xor_sync(0xFFFFFFFFu, acc[w], off);
    }

    // write the full 64-float row: squared sums in the spec segment, zeros elsewhere
    float* row = dens + (size_t)warp * (NTYPE * NWAVE);
    int lo = spec * NWAVE, hi = lo + NWAVE;
#pragma unroll
    for (int k = 0; k < 2; ++k) {
        int idx = lane + 32 * k;
        float v = (idx >= lo && idx < hi) ? acc[idx - lo] : 0.0f;
        row[idx] = v * v;
    }
}

// ---------------------------------------------------------------------------
// Launch
//   Inputs (metadata order): 0 coordinates, 1 shifts, 2 rs, 3 inta,
//                            4 params, 5 numatoms, 6 atom_index, 7 species
// ---------------------------------------------------------------------------
extern "C" void kernel_launch(void* const* d_in, const int* in_sizes, int n_in,
                              void* d_out, int out_size) {
    const float* coords     = (const float*)d_in[0];
    const float* shifts     = (const float*)d_in[1];
    const float* rs         = (const float*)d_in[2];
    const float* inta       = (const float*)d_in[3];
    const int*   atom_index = (const int*)d_in[6];
    const int*   species    = (const int*)d_in[7];
    float*       out        = (float*)d_out;

    zero_cnt_kernel<<<NATOM / 256, 256>>>();
    scatter_kernel<<<NPAIR / 256, 256>>>(coords, shifts, atom_index);
    gather_kernel<<<(NATOM * 32) / 256, 256>>>(rs, inta, species, out);
}

// round 14
// speedup vs baseline: 1.1718x; 1.1718x over previous
#include <cuda_runtime.h>
#include <cuda_bf16.h>
#include <cstdint>

// Problem constants (fixed shapes from reference)
#define NB    32
#define NA    1024
#define PPB   65536      // pairs per batch = NA * NEIGH
#define NTYPE 4
#define NWAVE 16
#define NPAIR (NB * PPB)                 // 2,097,152
#define NATOM (NB * NA)                  // 32,768
#define CAP   128                        // bucket capacity per atom (mean ~61)

// Scratch (device-global: allocation-free, module-load resident).
// g_cnt is zero-initialized at module load; gather_kernel resets each entry
// to 0 after consuming it, so every kernel_launch invocation (first run,
// graph replays) sees zeroed counters at scatter entry.
__device__ int   g_cnt[NATOM];
__device__ float g_bucket[(size_t)NATOM * CAP];   // 16 MB, L2-resident

// ---------------------------------------------------------------------------
// K1 (passA): per-pair distance, bucket scatter of r by center atom.
// Each block handles 256 consecutive pairs of ONE batch (256 blocks/batch),
// so the batch's 1024 coords are staged in smem -> LDS instead of diverged LDG.
// ---------------------------------------------------------------------------
__global__ void __launch_bounds__(256)
scatter_kernel(const float* __restrict__ coords,      // (NATOM, 3)
               const float* __restrict__ shifts,      // (NB*PPB, 3)
               const int*   __restrict__ atom_index)  // (NB, 2, PPB)
{
    __shared__ float4 s_c[NA];                       // 16 KB padded coords
    unsigned b = blockIdx.x >> 8;                    // 256 blocks per batch

    const float* cb = coords + (size_t)b * NA * 3u;
    for (int a = threadIdx.x; a < NA; a += 256) {
        const float* c = cb + 3 * a;
        s_c[a] = make_float4(c[0], c[1], c[2], 0.0f);
    }
    __syncthreads();

    unsigned p = blockIdx.x * 256u + threadIdx.x;    // exactly NPAIR threads
    unsigned j = p & (PPB - 1);

    const int* ai = atom_index + (size_t)b * 2u * PPB;
    int i0 = __ldg(ai + j);
    int i1 = __ldg(ai + PPB + j);

    const float* shp = shifts + 3ull * p;            // coalesced 12B/thread
    float sx = shp[0], sy = shp[1], sz = shp[2];
    bool valid = (sx > -1e9f) && (sy > -1e9f) && (sz > -1e9f);

    float4 c0 = s_c[i0];
    float4 c1 = s_c[i1];
    float dx = c0.x - c1.x + sx;
    float dy = c0.y - c1.y + sy;
    float dz = c0.z - c1.z + sz;
    float r = sqrtf(dx * dx + dy * dy + dz * dz);

    // fc == 0 exactly at r >= 5: skip entirely
    if (!valid || r >= 5.0f) return;

    unsigned g0 = (b << 10) + (unsigned)i0;          // NA = 2^10
    int slot = atomicAdd(&g_cnt[g0], 1);
    if (slot < CAP)                                  // overflow guard
        g_bucket[(size_t)g0 * CAP + slot] = r;
}

// ---------------------------------------------------------------------------
// K2 (passB): one warp per atom. Lane = (w, sub): w = lane&15, sub = lane>>4.
// Stage bucket as (r, fc) in smem; each lane accumulates its single w over
// its half of the pairs; ONE shfl_xor(16) finishes the reduction.
// Absorbs zero-fill and final square of the output, and resets g_cnt.
// ---------------------------------------------------------------------------
__global__ void __launch_bounds__(256)
gather_kernel(const float* __restrict__ rs,        // (NTYPE, NWAVE)
              const float* __restrict__ inta,      // (NTYPE, NWAVE)
              const int*   __restrict__ species,   // (NATOM)
              float*       __restrict__ dens)      // (NATOM, 64)
{
    __shared__ float  s_rs[NTYPE * NWAVE];
    __shared__ float  s_ia[NTYPE * NWAVE];
    __shared__ float2 s_bk[8][CAP];                 // 8 KB: one bucket per warp

    int t = threadIdx.x;
    if (t < NTYPE * NWAVE) {
        s_rs[t] = rs[t];
        s_ia[t] = inta[t];
    }
    __syncthreads();

    int wslot = t >> 5;
    int lane  = t & 31;
    int atom  = blockIdx.x * 8 + wslot;             // grid covers exactly NATOM warps

    int cnt = g_cnt[atom];
    if (lane == 0) g_cnt[atom] = 0;                 // self-clean for next launch
    if (cnt > CAP) cnt = CAP;
    int spec = __ldg(species + atom);

    int w   = lane & 15;
    int sub = lane >> 4;                            // 0 or 1
    float rw = s_rs[spec * NWAVE + w];
    float aw = -10.0f * s_ia[spec * NWAVE + w];

    // stage (r, fc) into smem — cos computed once per pair
    const float* bk = g_bucket + (size_t)atom * CAP;
    float2* sm = s_bk[wslot];
    for (int i = lane; i < cnt; i += 32) {
        float r  = bk[i];                           // coalesced within warp
        float fc = 0.5f * (__cosf(r * 0.628318530717958647692f) + 1.0f);
        sm[i] = make_float2(r, fc);
    }
    __syncwarp();

    float acc = 0.0f;
    for (int i = sub; i < cnt; i += 2) {            // broadcast LDS (2 addrs/warp)
        float2 rf = sm[i];
        float d = rf.x - rw;
        acc += rf.y * __expf(aw * d * d);
    }
    acc += __shfl_xor_sync(0xFFFFFFFFu, acc, 16);   // single-round reduction

    // write full 64-float row: squared sums in spec segment, zeros elsewhere.
    // For idx in [lo, lo+16): needed w = idx - lo = lane mod 16 = this lane's w.
    float v2 = acc * acc;
    float* row = dens + (size_t)atom * (NTYPE * NWAVE);
    int lo = spec * NWAVE;
    row[lane]      = ((unsigned)(lane      - lo) < 16u) ? v2 : 0.0f;
    row[lane + 32] = ((unsigned)(lane + 32 - lo) < 16u) ? v2 : 0.0f;
}

// ---------------------------------------------------------------------------
// Launch
//   Inputs (metadata order): 0 coordinates, 1 shifts, 2 rs, 3 inta,
//                            4 params, 5 numatoms, 6 atom_index, 7 species
// ---------------------------------------------------------------------------
extern "C" void kernel_launch(void* const* d_in, const int* in_sizes, int n_in,
                              void* d_out, int out_size) {
    const float* coords     = (const float*)d_in[0];
    const float* shifts     = (const float*)d_in[1];
    const float* rs         = (const float*)d_in[2];
    const float* inta       = (const float*)d_in[3];
    const int*   atom_index = (const int*)d_in[6];
    const int*   species    = (const int*)d_in[7];
    float*       out        = (float*)d_out;

    scatter_kernel<<<NPAIR / 256, 256>>>(coords, shifts, atom_index);
    gather_kernel<<<NATOM / 8, 256>>>(rs, inta, species, out);
}